// round 14
// baseline (speedup 1.0000x reference)
#include <cuda_runtime.h>
#include <cuda_fp16.h>
#include <math.h>
#include <stdint.h>

#define H 1024
#define F 2048
#define E 8
#define T 2048

// ---- gemm1 (R14): BK=64, 3-stage, cp.async A ----
#define BM 128
#define BN 64
#define BK1 64
#define SPH1 72
#define NS1 3
#define A1ST (BM * SPH1)
#define B1ST (BN * SPH1)
#define S1_A(s)  ((s) * A1ST)
#define S1_B1(s) (NS1 * A1ST + (s) * B1ST)
#define S1_B3(s) (NS1 * A1ST + NS1 * B1ST + (s) * B1ST)
#define G1_BYTES ((NS1 * A1ST + 2 * NS1 * B1ST) * 2)   // 110592

// ---- gemm2 (R13, unchanged): BK=64, 3-stage ----
#define BM2 128
#define BN2 128
#define BK2 64
#define SPH2 72
#define NSTG2 3
#define G2_AST (BM2 * SPH2)
#define G2_BST (BN2 * SPH2)
#define G2_A(s)  ((s) * G2_AST)
#define G2_B(s)  (NSTG2 * G2_AST + (s) * G2_BST)
#define G2_BYTES ((NSTG2 * (G2_AST + G2_BST)) * 2)     // 110592

// ---- scratch ----
__device__ int    g_cnt[E];
__device__ int    g_tok[E * T];
__device__ float  g_wgt[E * T];
__device__ __half g_x16[(size_t)T * H];       // fp16 x (written by router)
__device__ __half g_mid[(size_t)E * T * F];   // fp16 intermediate
__device__ __half g_w2h[(size_t)E * H * F];   // fp16 w2 (written by gemm1 prologue)

// ---------------------------------------------------------------
__device__ __forceinline__ void ldsm4(unsigned r[4], const __half* p) {
    unsigned a = (unsigned)__cvta_generic_to_shared(p);
    asm volatile("ldmatrix.sync.aligned.m8n8.x4.shared.b16 {%0,%1,%2,%3}, [%4];"
                 : "=r"(r[0]), "=r"(r[1]), "=r"(r[2]), "=r"(r[3]) : "r"(a));
}
__device__ __forceinline__ void mma16(float c[4], const unsigned a[4], unsigned b0, unsigned b1) {
    asm volatile(
        "mma.sync.aligned.m16n8k16.row.col.f32.f16.f16.f32 "
        "{%0,%1,%2,%3},{%4,%5,%6,%7},{%8,%9},{%0,%1,%2,%3};"
        : "+f"(c[0]), "+f"(c[1]), "+f"(c[2]), "+f"(c[3])
        : "r"(a[0]), "r"(a[1]), "r"(a[2]), "r"(a[3]), "r"(b0), "r"(b1));
}
__device__ __forceinline__ uint2 f4h(float4 v) {
    __half2 lo = __floats2half2_rn(v.x, v.y);
    __half2 hi = __floats2half2_rn(v.z, v.w);
    uint2 r;
    r.x = *(unsigned*)&lo; r.y = *(unsigned*)&hi;
    return r;
}
__device__ __forceinline__ void cp_async16(const __half* sdst, const __half* gsrc) {
    unsigned d = (unsigned)__cvta_generic_to_shared(sdst);
    asm volatile("cp.async.cg.shared.global [%0], [%1], 16;" :: "r"(d), "l"(gsrc));
}
#define CP_COMMIT() asm volatile("cp.async.commit_group;" ::: "memory")
#define CP_WAIT0()  asm volatile("cp.async.wait_group 0;" ::: "memory")
#define CP_WAIT1()  asm volatile("cp.async.wait_group 1;" ::: "memory")

// ---------------------------------------------------------------
__global__ void zero_cnt_kernel() {
    if (threadIdx.x < E) g_cnt[threadIdx.x] = 0;
}

// ---------------------------------------------------------------
// Router (fused x fp32->fp16 copy): one warp per token.
__global__ __launch_bounds__(256) void router_kernel(
    const float* __restrict__ x, const float* __restrict__ gw,
    float* __restrict__ logits_out)
{
    const int t    = blockIdx.x * 8 + (threadIdx.x >> 5);
    const int lane = threadIdx.x & 31;
    const float4* xr  = (const float4*)(x + (size_t)t * H);
    const float4* gw4 = (const float4*)gw;
    __half* xo = g_x16 + (size_t)t * H;

    float acc[E];
#pragma unroll
    for (int e = 0; e < E; e++) acc[e] = 0.f;

#pragma unroll
    for (int i = 0; i < 8; i++) {
        float4 xv = xr[i * 32 + lane];
        *(uint2*)(xo + (i * 32 + lane) * 4) = f4h(xv);
#pragma unroll
        for (int e = 0; e < E; e++) {
            float4 g = gw4[e * 256 + i * 32 + lane];
            acc[e] += xv.x * g.x + xv.y * g.y + xv.z * g.z + xv.w * g.w;
        }
    }
#pragma unroll
    for (int e = 0; e < E; e++)
#pragma unroll
        for (int o = 16; o > 0; o >>= 1)
            acc[e] += __shfl_xor_sync(0xffffffffu, acc[e], o);

    if (lane == 0) {
        if (logits_out)
#pragma unroll
            for (int e = 0; e < E; e++) logits_out[(size_t)t * E + e] = acc[e];
        int i1 = 0;
#pragma unroll
        for (int e = 1; e < E; e++) if (acc[e] > acc[i1]) i1 = e;
        int i2 = -1;
#pragma unroll
        for (int e = 0; e < E; e++) {
            if (e == i1) continue;
            if (i2 < 0 || acc[e] > acc[i2]) i2 = e;
        }
        float wa = 1.f / (1.f + expf(acc[i2] - acc[i1]));
        float wb = 1.f - wa;
        int s1 = atomicAdd(&g_cnt[i1], 1);
        g_tok[i1 * T + s1] = t; g_wgt[i1 * T + s1] = wa;
        int s2 = atomicAdd(&g_cnt[i2], 1);
        g_tok[i2 * T + s2] = t; g_wgt[i2 * T + s2] = wb;
    }
}

// ---------------------------------------------------------------
// GEMM1 (R14): BK=64, 3-stage cp.async A (fp16 x), two-wave fp32 B, + w2 conv.
// Grid must be exactly 4096 blocks (32 x 16 x 8): each converts 1024 float4 of w2.
__global__ __launch_bounds__(256, 2) void gemm1_kernel(
    const float* __restrict__ w1,
    const float* __restrict__ w3,
    const float* __restrict__ w2)
{
    extern __shared__ __align__(16) __half sm[];
    const int tid = threadIdx.x;

    // ---- w2 conversion share (before any early exit) ----
    {
        int bflat = blockIdx.x + gridDim.x * (blockIdx.y + gridDim.y * blockIdx.z);
        const float4* src = (const float4*)w2 + (size_t)bflat * 1024;
        uint2* dst = (uint2*)g_w2h + (size_t)bflat * 1024;
#pragma unroll
        for (int j = 0; j < 4; j++)
            dst[j * 256 + tid] = f4h(src[j * 256 + tid]);
    }

    const int e  = blockIdx.z;
    const int n0 = blockIdx.x * BN;
    const int m0 = blockIdx.y * BM;
    const int ne = g_cnt[e];
    if (m0 >= ne) return;

    const int lane = tid & 31, wid = tid >> 5;
    const int wm   = (wid & 3) * 32, wn = (wid >> 2) * 32;

    // A loader (cp.async, 4 granules/thread): rows lrow+32i, col8=(tid&7)*8 halfs
    const int lrow = tid >> 3, lc8 = (tid & 7) * 8;
    const __half* amp[4];
#pragma unroll
    for (int r = 0; r < 4; r++) {
        int m = m0 + lrow + 32 * r;
        int idx = (m < ne) ? m : (ne - 1);
        amp[r] = g_x16 + (size_t)g_tok[e * T + idx] * H + lc8;
    }
    // B loaders: row = tid>>2 (0..63), colbase=(tid&3)*8; 2 float4 per tensor per wave
    const int brow = tid >> 2, bcb = (tid & 3) * 8;
    const float* b1p = w1 + ((size_t)e * F + n0 + brow) * H + bcb;
    const float* b3p = w3 + ((size_t)e * F + n0 + brow) * H + bcb;

    float4 v1a, v1b, v3a, v3b;
    float acc1[2][4][4] = {}, acc3[2][4][4] = {};

    const int NC = H / BK1;   // 16

    // ---- prologue: A stages 0,1 in flight; B chunk0 stored directly ----
#pragma unroll
    for (int s = 0; s < 2; s++) {
#pragma unroll
        for (int i = 0; i < 4; i++)
            cp_async16(&sm[S1_A(s) + (lrow + 32 * i) * SPH1 + lc8], amp[i] + s * BK1);
        CP_COMMIT();
    }
#pragma unroll
    for (int w = 0; w < 2; w++) {
        v1a = *(const float4*)(b1p + w * 32);
        v1b = *(const float4*)(b1p + w * 32 + 4);
        v3a = *(const float4*)(b3p + w * 32);
        v3b = *(const float4*)(b3p + w * 32 + 4);
        *(uint2*)&sm[S1_B1(0) + brow * SPH1 + w * 32 + bcb]     = f4h(v1a);
        *(uint2*)&sm[S1_B1(0) + brow * SPH1 + w * 32 + bcb + 4] = f4h(v1b);
        *(uint2*)&sm[S1_B3(0) + brow * SPH1 + w * 32 + bcb]     = f4h(v3a);
        *(uint2*)&sm[S1_B3(0) + brow * SPH1 + w * 32 + bcb + 4] = f4h(v3b);
    }
    CP_WAIT1();
    __syncthreads();

    int cur = 0;
    for (int c = 0; c < NC; c++) {
        const int  nxt   = (cur + 1 == NS1) ? 0 : cur + 1;
        const bool more  = (c + 1 < NC);
        const bool have2 = (c + 2 < NC);
        const int  k1    = (c + 1) * BK1;

        if (have2) {
            int s  = (nxt + 1 == NS1) ? 0 : nxt + 1;
            int k2 = (c + 2) * BK1;
#pragma unroll
            for (int i = 0; i < 4; i++)
                cp_async16(&sm[S1_A(s) + (lrow + 32 * i) * SPH1 + lc8], amp[i] + k2);
            CP_COMMIT();
        }
        if (more) {   // B(c+1) wave 0
            v1a = *(const float4*)(b1p + k1);
            v1b = *(const float4*)(b1p + k1 + 4);
            v3a = *(const float4*)(b3p + k1);
            v3b = *(const float4*)(b3p + k1 + 4);
        }

        // ---- compute kk = 0,16 ----
#pragma unroll
        for (int kk = 0; kk < 32; kk += 16) {
            unsigned a[2][4];
#pragma unroll
            for (int mt = 0; mt < 2; mt++)
                ldsm4(a[mt], &sm[S1_A(cur) + (wm + mt * 16 + (lane & 15)) * SPH1 + kk + (lane >> 4) * 8]);
            unsigned b1f[2][4], b3f[2][4];
#pragma unroll
            for (int bh = 0; bh < 2; bh++) {
                int row = wn + bh * 16 + ((lane >> 4) & 1) * 8 + (lane & 7);
                int col = kk + ((lane >> 3) & 1) * 8;
                ldsm4(b1f[bh], &sm[S1_B1(cur) + row * SPH1 + col]);
                ldsm4(b3f[bh], &sm[S1_B3(cur) + row * SPH1 + col]);
            }
#pragma unroll
            for (int mt = 0; mt < 2; mt++)
#pragma unroll
                for (int nt = 0; nt < 4; nt++) {
                    int bh = nt >> 1, pr = (nt & 1) * 2;
                    mma16(acc1[mt][nt], a[mt], b1f[bh][pr], b1f[bh][pr + 1]);
                    mma16(acc3[mt][nt], a[mt], b3f[bh][pr], b3f[bh][pr + 1]);
                }
        }

        if (more) {   // store wave 0 -> nxt; load wave 1
            *(uint2*)&sm[S1_B1(nxt) + brow * SPH1 + bcb]     = f4h(v1a);
            *(uint2*)&sm[S1_B1(nxt) + brow * SPH1 + bcb + 4] = f4h(v1b);
            *(uint2*)&sm[S1_B3(nxt) + brow * SPH1 + bcb]     = f4h(v3a);
            *(uint2*)&sm[S1_B3(nxt) + brow * SPH1 + bcb + 4] = f4h(v3b);
            v1a = *(const float4*)(b1p + k1 + 32);
            v1b = *(const float4*)(b1p + k1 + 36);
            v3a = *(const float4*)(b3p + k1 + 32);
            v3b = *(const float4*)(b3p + k1 + 36);
        }

        // ---- compute kk = 32,48 ----
#pragma unroll
        for (int kk = 32; kk < 64; kk += 16) {
            unsigned a[2][4];
#pragma unroll
            for (int mt = 0; mt < 2; mt++)
                ldsm4(a[mt], &sm[S1_A(cur) + (wm + mt * 16 + (lane & 15)) * SPH1 + kk + (lane >> 4) * 8]);
            unsigned b1f[2][4], b3f[2][4];
#pragma unroll
            for (int bh = 0; bh < 2; bh++) {
                int row = wn + bh * 16 + ((lane >> 4) & 1) * 8 + (lane & 7);
                int col = kk + ((lane >> 3) & 1) * 8;
                ldsm4(b1f[bh], &sm[S1_B1(cur) + row * SPH1 + col]);
                ldsm4(b3f[bh], &sm[S1_B3(cur) + row * SPH1 + col]);
            }
#pragma unroll
            for (int mt = 0; mt < 2; mt++)
#pragma unroll
                for (int nt = 0; nt < 4; nt++) {
                    int bh = nt >> 1, pr = (nt & 1) * 2;
                    mma16(acc1[mt][nt], a[mt], b1f[bh][pr], b1f[bh][pr + 1]);
                    mma16(acc3[mt][nt], a[mt], b3f[bh][pr], b3f[bh][pr + 1]);
                }
        }

        if (more) {   // store wave 1; advance
            *(uint2*)&sm[S1_B1(nxt) + brow * SPH1 + 32 + bcb]     = f4h(v1a);
            *(uint2*)&sm[S1_B1(nxt) + brow * SPH1 + 32 + bcb + 4] = f4h(v1b);
            *(uint2*)&sm[S1_B3(nxt) + brow * SPH1 + 32 + bcb]     = f4h(v3a);
            *(uint2*)&sm[S1_B3(nxt) + brow * SPH1 + 32 + bcb + 4] = f4h(v3b);
            if (have2) CP_WAIT1(); else CP_WAIT0();
            __syncthreads();
            cur = nxt;
        }
    }

    // ---- epilogue: SwiGLU -> g_mid (fp16) ----
    const int g = lane >> 2, tg = lane & 3;
#pragma unroll
    for (int mt = 0; mt < 2; mt++)
#pragma unroll
        for (int half = 0; half < 2; half++) {
            int m = m0 + wm + mt * 16 + g + half * 8;
            if (m >= ne) continue;
            __half* dst = g_mid + ((size_t)e * T + m) * F + n0 + wn;
#pragma unroll
            for (int nt = 0; nt < 4; nt++) {
                float h0 = acc1[mt][nt][half * 2 + 0];
                float h1 = acc1[mt][nt][half * 2 + 1];
                float g0 = acc3[mt][nt][half * 2 + 0];
                float g1 = acc3[mt][nt][half * 2 + 1];
                float r0 = h0 / (1.f + __expf(-h0)) * g0;
                float r1 = h1 / (1.f + __expf(-h1)) * g1;
                *(__half2*)(dst + nt * 8 + tg * 2) = __floats2half2_rn(r0, r1);
            }
        }
}

// ---------------------------------------------------------------
// GEMM2 (R13, unchanged): BK=64, 3 stages, all cp.async.
__global__ __launch_bounds__(256, 2) void gemm2_kernel(
    float* __restrict__ out)
{
    extern __shared__ __align__(16) __half sm[];
    const int e  = blockIdx.z;
    const int n0 = blockIdx.x * BN2;
    const int m0 = blockIdx.y * BM2;
    const int ne = g_cnt[e];
    if (m0 >= ne) return;

    const int tid  = threadIdx.x;
    const int lane = tid & 31, wid = tid >> 5;
    const int wm   = (wid & 3) * 32, wn = (wid >> 2) * 64;

    const int lrow = tid >> 3, lc8 = (tid & 7) * 8;
    const __half* amb = g_mid + ((size_t)e * T + m0 + lrow) * F + lc8;
    const __half* bmb = g_w2h + ((size_t)e * H + n0 + lrow) * F + lc8;

    float acc[2][8][4] = {};

#pragma unroll
    for (int s = 0; s < 2; s++) {
#pragma unroll
        for (int i = 0; i < 4; i++) {
            int row = lrow + 32 * i;
            cp_async16(&sm[G2_A(s) + row * SPH2 + lc8], amb + (size_t)(32 * i) * F + s * BK2);
            cp_async16(&sm[G2_B(s) + row * SPH2 + lc8], bmb + (size_t)(32 * i) * F + s * BK2);
        }
        CP_COMMIT();
    }
    CP_WAIT1();
    __syncthreads();

    const int NC = F / BK2;   // 32
    int cur = 0;
    for (int c = 0; c < NC; c++) {
        const bool have2 = (c + 2 < NC);
        if (have2) {
            int s = (cur + 2) % NSTG2;
            int k0 = (c + 2) * BK2;
#pragma unroll
            for (int i = 0; i < 4; i++) {
                int row = lrow + 32 * i;
                cp_async16(&sm[G2_A(s) + row * SPH2 + lc8], amb + (size_t)(32 * i) * F + k0);
                cp_async16(&sm[G2_B(s) + row * SPH2 + lc8], bmb + (size_t)(32 * i) * F + k0);
            }
            CP_COMMIT();
        }

#pragma unroll
        for (int kk = 0; kk < BK2; kk += 16) {
            unsigned a[2][4];
#pragma unroll
            for (int mt = 0; mt < 2; mt++)
                ldsm4(a[mt], &sm[G2_A(cur) + (wm + mt * 16 + (lane & 15)) * SPH2 + kk + (lane >> 4) * 8]);
            unsigned bf[4][4];
#pragma unroll
            for (int bh = 0; bh < 4; bh++) {
                int row = wn + bh * 16 + ((lane >> 4) & 1) * 8 + (lane & 7);
                int col = kk + ((lane >> 3) & 1) * 8;
                ldsm4(bf[bh], &sm[G2_B(cur) + row * SPH2 + col]);
            }
#pragma unroll
            for (int mt = 0; mt < 2; mt++)
#pragma unroll
                for (int nt = 0; nt < 8; nt++) {
                    int bh = nt >> 1, pr = (nt & 1) * 2;
                    mma16(acc[mt][nt], a[mt], bf[bh][pr], bf[bh][pr + 1]);
                }
        }

        if (c + 1 < NC) {
            if (have2) CP_WAIT1(); else CP_WAIT0();
            __syncthreads();
            cur = (cur + 1 == NSTG2) ? 0 : cur + 1;
        }
    }

    const int g = lane >> 2, tg = lane & 3;
#pragma unroll
    for (int mt = 0; mt < 2; mt++)
#pragma unroll
        for (int half = 0; half < 2; half++) {
            int m = m0 + wm + mt * 16 + g + half * 8;
            if (m >= ne) continue;
            int   tok = g_tok[e * T + m];
            float w   = g_wgt[e * T + m];
            float* dst = out + (size_t)tok * H + n0 + wn;
#pragma unroll
            for (int nt = 0; nt < 8; nt++) {
                atomicAdd(dst + nt * 8 + tg * 2 + 0, w * acc[mt][nt][half * 2 + 0]);
                atomicAdd(dst + nt * 8 + tg * 2 + 1, w * acc[mt][nt][half * 2 + 1]);
            }
        }
}

// ---------------------------------------------------------------
extern "C" void kernel_launch(void* const* d_in, const int* in_sizes, int n_in,
                              void* d_out, int out_size)
{
    const float* x  = (const float*)d_in[0];
    const float* gw = (const float*)d_in[1];
    const float* w1 = (const float*)d_in[2];
    const float* w2 = (const float*)d_in[3];
    const float* w3 = (const float*)d_in[4];
    float* out = (float*)d_out;

    static int configured = 0;
    if (!configured) {
        cudaFuncSetAttribute(gemm1_kernel,
            cudaFuncAttributeMaxDynamicSharedMemorySize, G1_BYTES);
        cudaFuncSetAttribute(gemm2_kernel,
            cudaFuncAttributeMaxDynamicSharedMemorySize, G2_BYTES);
        configured = 1;
    }

    const size_t main_sz = (size_t)T * H;
    float* logits = ((size_t)out_size >= main_sz + (size_t)T * E)
                        ? out + main_sz : nullptr;

    cudaMemsetAsync(d_out, 0, (size_t)out_size * sizeof(float));
    zero_cnt_kernel<<<1, 32>>>();
    router_kernel<<<T / 8, 256>>>(x, gw, logits);
    // grid = 32*16*8 = 4096 blocks; each converts 1024 float4 of w2
    gemm1_kernel<<<dim3(F / BN, T / BM, E), 256, G1_BYTES>>>(w1, w3, w2);
    gemm2_kernel<<<dim3(H / BN2, T / BM2, E), 256, G2_BYTES>>>(out);
}

// round 15
// speedup vs baseline: 1.0251x; 1.0251x over previous
#include <cuda_runtime.h>
#include <cuda_fp16.h>
#include <math.h>
#include <stdint.h>

#define H 1024
#define F 2048
#define E 8
#define T 2048

// ---- gemm1 tiles (R6/R13) ----
#define BM 128
#define BN 64
#define BK 32
#define SPH 40   // smem row stride in halfs; ldmatrix conflict-free

// ---- gemm2 tiles (R13): BK=64, 3-stage ----
#define BM2 128
#define BN2 128
#define BK2 64
#define SPH2 72
#define NSTG2 3

#define G2_AST (BM2 * SPH2)
#define G2_BST (BN2 * SPH2)
#define G2_A(s)  ((s) * G2_AST)
#define G2_B(s)  (NSTG2 * G2_AST + (s) * G2_BST)
#define G2_BYTES ((NSTG2 * (G2_AST + G2_BST)) * 2)   // 110592

// ---- scratch (device globals: allocation-free per harness rules) ----
__device__ int    g_cnt[E];
__device__ int    g_tok[E * T];
__device__ float  g_wgt[E * T];
__device__ __half g_mid[(size_t)E * T * F];   // [E][T][F] fp16 compacted rows
__device__ __half g_w2h[(size_t)E * H * F];   // fp16 copy of w2 (filled in gemm1)

// ---------------------------------------------------------------
__device__ __forceinline__ void ldsm4(unsigned r[4], const __half* p) {
    unsigned a = (unsigned)__cvta_generic_to_shared(p);
    asm volatile("ldmatrix.sync.aligned.m8n8.x4.shared.b16 {%0,%1,%2,%3}, [%4];"
                 : "=r"(r[0]), "=r"(r[1]), "=r"(r[2]), "=r"(r[3]) : "r"(a));
}
__device__ __forceinline__ void mma16(float c[4], const unsigned a[4], unsigned b0, unsigned b1) {
    asm volatile(
        "mma.sync.aligned.m16n8k16.row.col.f32.f16.f16.f32 "
        "{%0,%1,%2,%3},{%4,%5,%6,%7},{%8,%9},{%0,%1,%2,%3};"
        : "+f"(c[0]), "+f"(c[1]), "+f"(c[2]), "+f"(c[3])
        : "r"(a[0]), "r"(a[1]), "r"(a[2]), "r"(a[3]), "r"(b0), "r"(b1));
}
__device__ __forceinline__ uint2 f4h(float4 v) {
    __half2 lo = __floats2half2_rn(v.x, v.y);
    __half2 hi = __floats2half2_rn(v.z, v.w);
    uint2 r;
    r.x = *(unsigned*)&lo; r.y = *(unsigned*)&hi;
    return r;
}
__device__ __forceinline__ void cp_async16(const __half* sdst, const __half* gsrc) {
    unsigned d = (unsigned)__cvta_generic_to_shared(sdst);
    asm volatile("cp.async.cg.shared.global [%0], [%1], 16;" :: "r"(d), "l"(gsrc));
}
#define CP_COMMIT() asm volatile("cp.async.commit_group;" ::: "memory")
#define CP_WAIT0()  asm volatile("cp.async.wait_group 0;" ::: "memory")
#define CP_WAIT1()  asm volatile("cp.async.wait_group 1;" ::: "memory")

// ---------------------------------------------------------------
// Router: one warp per token.
__global__ __launch_bounds__(256) void router_kernel(
    const float* __restrict__ x, const float* __restrict__ gw,
    float* __restrict__ logits_out)
{
    const int t    = blockIdx.x * 8 + (threadIdx.x >> 5);
    const int lane = threadIdx.x & 31;
    const float4* xr  = (const float4*)(x + (size_t)t * H);
    const float4* gw4 = (const float4*)gw;

    float acc[E];
#pragma unroll
    for (int e = 0; e < E; e++) acc[e] = 0.f;

#pragma unroll
    for (int i = 0; i < 8; i++) {
        float4 xv = xr[i * 32 + lane];
#pragma unroll
        for (int e = 0; e < E; e++) {
            float4 g = gw4[e * 256 + i * 32 + lane];
            acc[e] += xv.x * g.x + xv.y * g.y + xv.z * g.z + xv.w * g.w;
        }
    }
#pragma unroll
    for (int e = 0; e < E; e++)
#pragma unroll
        for (int o = 16; o > 0; o >>= 1)
            acc[e] += __shfl_xor_sync(0xffffffffu, acc[e], o);

    if (lane == 0) {
        if (logits_out)
#pragma unroll
            for (int e = 0; e < E; e++) logits_out[(size_t)t * E + e] = acc[e];
        int i1 = 0;
#pragma unroll
        for (int e = 1; e < E; e++) if (acc[e] > acc[i1]) i1 = e;
        int i2 = -1;
#pragma unroll
        for (int e = 0; e < E; e++) {
            if (e == i1) continue;
            if (i2 < 0 || acc[e] > acc[i2]) i2 = e;
        }
        float wa = 1.f / (1.f + expf(acc[i2] - acc[i1]));
        float wb = 1.f - wa;
        int s1 = atomicAdd(&g_cnt[i1], 1);
        g_tok[i1 * T + s1] = t; g_wgt[i1 * T + s1] = wa;
        int s2 = atomicAdd(&g_cnt[i2], 1);
        g_tok[i2 * T + s2] = t; g_wgt[i2 * T + s2] = wb;
    }
}

// ---------------------------------------------------------------
// GEMM1 (R13 structure) + latency-hidden w2 fp32->fp16 conversion.
// Grid must be exactly 4096 blocks (32 x 16 x 8): each converts 1024 float4 of w2.
__global__ __launch_bounds__(256, 2) void gemm1_kernel(
    const float* __restrict__ x,
    const float* __restrict__ w1,
    const float* __restrict__ w3,
    const float* __restrict__ w2)
{
    const int tid = threadIdx.x;

    // ---- w2 conversion: issue LDGs FIRST (latency hidden by setup below) ----
    const int bflat = blockIdx.x + gridDim.x * (blockIdx.y + gridDim.y * blockIdx.z);
    const float4* csrc = (const float4*)w2 + (size_t)bflat * 1024;
    float4 cv0 = csrc[0 * 256 + tid];
    float4 cv1 = csrc[1 * 256 + tid];
    float4 cv2 = csrc[2 * 256 + tid];
    float4 cv3 = csrc[3 * 256 + tid];

    const int e  = blockIdx.z;
    const int n0 = blockIdx.x * BN;
    const int m0 = blockIdx.y * BM;
    const int ne = g_cnt[e];

    __shared__ __align__(16) __half sA [2][BM * SPH];
    __shared__ __align__(16) __half sB1[2][BN * SPH];
    __shared__ __align__(16) __half sB3[2][BN * SPH];

    const int lane = tid & 31, wid = tid >> 5;
    const int wm   = (wid & 3) * 32, wn = (wid >> 2) * 32;

    const int lrow = tid >> 3, lc4 = tid & 7;

    // ---- index setup (covers conv LDG latency) ----
    const float* ap[4];
#pragma unroll
    for (int r = 0; r < 4; r++) {
        int m = m0 + lrow + 32 * r;
        int idx = (m < ne) ? m : ((ne > 0) ? (ne - 1) : 0);
        ap[r] = x + (size_t)g_tok[e * T + idx] * H + lc4 * 4;
    }
    const float* b1p[2];
    const float* b3p[2];
#pragma unroll
    for (int r = 0; r < 2; r++) {
        b1p[r] = w1 + ((size_t)e * F + n0 + lrow + 32 * r) * H + lc4 * 4;
        b3p[r] = w3 + ((size_t)e * F + n0 + lrow + 32 * r) * H + lc4 * 4;
    }

    // ---- store converted w2 (LDGs have had ~setup time to land) ----
    {
        uint2* cdst = (uint2*)g_w2h + (size_t)bflat * 1024;
        cdst[0 * 256 + tid] = f4h(cv0);
        cdst[1 * 256 + tid] = f4h(cv1);
        cdst[2 * 256 + tid] = f4h(cv2);
        cdst[3 * 256 + tid] = f4h(cv3);
    }
    if (m0 >= ne) return;

    float4 va[4], vb1[2], vb3[2];
    float acc1[2][4][4] = {}, acc3[2][4][4] = {};

#pragma unroll
    for (int r = 0; r < 4; r++) va[r] = *(const float4*)(ap[r]);
#pragma unroll
    for (int r = 0; r < 2; r++) { vb1[r] = *(const float4*)(b1p[r]); vb3[r] = *(const float4*)(b3p[r]); }
#pragma unroll
    for (int r = 0; r < 4; r++) *(uint2*)&sA[0][(lrow + 32 * r) * SPH + lc4 * 4] = f4h(va[r]);
#pragma unroll
    for (int r = 0; r < 2; r++) {
        *(uint2*)&sB1[0][(lrow + 32 * r) * SPH + lc4 * 4] = f4h(vb1[r]);
        *(uint2*)&sB3[0][(lrow + 32 * r) * SPH + lc4 * 4] = f4h(vb3[r]);
    }
    __syncthreads();

    int cur = 0;
    for (int chunk = 1; chunk <= H / BK; chunk++) {
        if (chunk < H / BK) {
            int k0 = chunk * BK;
#pragma unroll
            for (int r = 0; r < 4; r++) va[r] = *(const float4*)(ap[r] + k0);
#pragma unroll
            for (int r = 0; r < 2; r++) { vb1[r] = *(const float4*)(b1p[r] + k0); vb3[r] = *(const float4*)(b3p[r] + k0); }
        }
#pragma unroll
        for (int kk = 0; kk < BK; kk += 16) {
            unsigned a[2][4];
#pragma unroll
            for (int mt = 0; mt < 2; mt++)
                ldsm4(a[mt], &sA[cur][(wm + mt * 16 + (lane & 15)) * SPH + kk + (lane >> 4) * 8]);
            unsigned b1f[2][4], b3f[2][4];
#pragma unroll
            for (int bh = 0; bh < 2; bh++) {
                int row = wn + bh * 16 + ((lane >> 4) & 1) * 8 + (lane & 7);
                int col = kk + ((lane >> 3) & 1) * 8;
                ldsm4(b1f[bh], &sB1[cur][row * SPH + col]);
                ldsm4(b3f[bh], &sB3[cur][row * SPH + col]);
            }
#pragma unroll
            for (int mt = 0; mt < 2; mt++)
#pragma unroll
                for (int nt = 0; nt < 4; nt++) {
                    int bh = nt >> 1, pr = (nt & 1) * 2;
                    mma16(acc1[mt][nt], a[mt], b1f[bh][pr], b1f[bh][pr + 1]);
                    mma16(acc3[mt][nt], a[mt], b3f[bh][pr], b3f[bh][pr + 1]);
                }
        }
        if (chunk < H / BK) {
            int nxt = cur ^ 1;
#pragma unroll
            for (int r = 0; r < 4; r++) *(uint2*)&sA[nxt][(lrow + 32 * r) * SPH + lc4 * 4] = f4h(va[r]);
#pragma unroll
            for (int r = 0; r < 2; r++) {
                *(uint2*)&sB1[nxt][(lrow + 32 * r) * SPH + lc4 * 4] = f4h(vb1[r]);
                *(uint2*)&sB3[nxt][(lrow + 32 * r) * SPH + lc4 * 4] = f4h(vb3[r]);
            }
            __syncthreads();
            cur = nxt;
        }
    }

    const int g = lane >> 2, tg = lane & 3;
#pragma unroll
    for (int mt = 0; mt < 2; mt++)
#pragma unroll
        for (int half = 0; half < 2; half++) {
            int m = m0 + wm + mt * 16 + g + half * 8;
            if (m >= ne) continue;
            __half* dst = g_mid + ((size_t)e * T + m) * F + n0 + wn;
#pragma unroll
            for (int nt = 0; nt < 4; nt++) {
                float h0 = acc1[mt][nt][half * 2 + 0];
                float h1 = acc1[mt][nt][half * 2 + 1];
                float g0 = acc3[mt][nt][half * 2 + 0];
                float g1 = acc3[mt][nt][half * 2 + 1];
                float r0 = h0 / (1.f + __expf(-h0)) * g0;
                float r1 = h1 / (1.f + __expf(-h1)) * g1;
                __half2 v = __floats2half2_rn(r0, r1);
                *(__half2*)(dst + nt * 8 + tg * 2) = v;
            }
        }
}

// ---------------------------------------------------------------
// GEMM2 (R13, unchanged): BK=64, 3 stages, all cp.async from fp16 buffers.
__global__ __launch_bounds__(256, 2) void gemm2_kernel(
    float* __restrict__ out)
{
    extern __shared__ __align__(16) __half sm[];
    const int e  = blockIdx.z;
    const int n0 = blockIdx.x * BN2;
    const int m0 = blockIdx.y * BM2;
    const int ne = g_cnt[e];
    if (m0 >= ne) return;

    const int tid  = threadIdx.x;
    const int lane = tid & 31, wid = tid >> 5;
    const int wm   = (wid & 3) * 32, wn = (wid >> 2) * 64;

    const int lrow = tid >> 3, lc8 = (tid & 7) * 8;
    const __half* amb = g_mid + ((size_t)e * T + m0 + lrow) * F + lc8;
    const __half* bmb = g_w2h + ((size_t)e * H + n0 + lrow) * F + lc8;

    float acc[2][8][4] = {};

#pragma unroll
    for (int s = 0; s < 2; s++) {
#pragma unroll
        for (int i = 0; i < 4; i++) {
            int row = lrow + 32 * i;
            cp_async16(&sm[G2_A(s) + row * SPH2 + lc8], amb + (size_t)(32 * i) * F + s * BK2);
            cp_async16(&sm[G2_B(s) + row * SPH2 + lc8], bmb + (size_t)(32 * i) * F + s * BK2);
        }
        CP_COMMIT();
    }
    CP_WAIT1();
    __syncthreads();

    const int NC = F / BK2;   // 32
    int cur = 0;
    for (int c = 0; c < NC; c++) {
        const bool have2 = (c + 2 < NC);
        if (have2) {
            int s = (cur + 2) % NSTG2;
            int k0 = (c + 2) * BK2;
#pragma unroll
            for (int i = 0; i < 4; i++) {
                int row = lrow + 32 * i;
                cp_async16(&sm[G2_A(s) + row * SPH2 + lc8], amb + (size_t)(32 * i) * F + k0);
                cp_async16(&sm[G2_B(s) + row * SPH2 + lc8], bmb + (size_t)(32 * i) * F + k0);
            }
            CP_COMMIT();
        }

#pragma unroll
        for (int kk = 0; kk < BK2; kk += 16) {
            unsigned a[2][4];
#pragma unroll
            for (int mt = 0; mt < 2; mt++)
                ldsm4(a[mt], &sm[G2_A(cur) + (wm + mt * 16 + (lane & 15)) * SPH2 + kk + (lane >> 4) * 8]);
            unsigned bf[4][4];
#pragma unroll
            for (int bh = 0; bh < 4; bh++) {
                int row = wn + bh * 16 + ((lane >> 4) & 1) * 8 + (lane & 7);
                int col = kk + ((lane >> 3) & 1) * 8;
                ldsm4(bf[bh], &sm[G2_B(cur) + row * SPH2 + col]);
            }
#pragma unroll
            for (int mt = 0; mt < 2; mt++)
#pragma unroll
                for (int nt = 0; nt < 8; nt++) {
                    int bh = nt >> 1, pr = (nt & 1) * 2;
                    mma16(acc[mt][nt], a[mt], bf[bh][pr], bf[bh][pr + 1]);
                }
        }

        if (c + 1 < NC) {
            if (have2) CP_WAIT1(); else CP_WAIT0();
            __syncthreads();
            cur = (cur + 1 == NSTG2) ? 0 : cur + 1;
        }
    }

    const int g = lane >> 2, tg = lane & 3;
#pragma unroll
    for (int mt = 0; mt < 2; mt++)
#pragma unroll
        for (int half = 0; half < 2; half++) {
            int m = m0 + wm + mt * 16 + g + half * 8;
            if (m >= ne) continue;
            int   tok = g_tok[e * T + m];
            float w   = g_wgt[e * T + m];
            float* dst = out + (size_t)tok * H + n0 + wn;
#pragma unroll
            for (int nt = 0; nt < 8; nt++) {
                atomicAdd(dst + nt * 8 + tg * 2 + 0, w * acc[mt][nt][half * 2 + 0]);
                atomicAdd(dst + nt * 8 + tg * 2 + 1, w * acc[mt][nt][half * 2 + 1]);
            }
        }
}

// ---------------------------------------------------------------
extern "C" void kernel_launch(void* const* d_in, const int* in_sizes, int n_in,
                              void* d_out, int out_size)
{
    const float* x  = (const float*)d_in[0];
    const float* gw = (const float*)d_in[1];
    const float* w1 = (const float*)d_in[2];
    const float* w2 = (const float*)d_in[3];
    const float* w3 = (const float*)d_in[4];
    float* out = (float*)d_out;

    static int configured = 0;
    if (!configured) {
        cudaFuncSetAttribute(gemm2_kernel,
            cudaFuncAttributeMaxDynamicSharedMemorySize, G2_BYTES);
        configured = 1;
    }

    const size_t main_sz = (size_t)T * H;
    float* logits = ((size_t)out_size >= main_sz + (size_t)T * E)
                        ? out + main_sz : nullptr;

    // zero g_cnt via memset (drops the zero_cnt kernel launch)
    void* cnt_ptr = nullptr;
    cudaGetSymbolAddress(&cnt_ptr, g_cnt);

    cudaMemsetAsync(d_out, 0, (size_t)out_size * sizeof(float));
    cudaMemsetAsync(cnt_ptr, 0, E * sizeof(int));
    router_kernel<<<T / 8, 256>>>(x, gw, logits);
    // grid = 32*16*8 = 4096 blocks; each converts 1024 float4 of w2
    gemm1_kernel<<<dim3(F / BN, T / BM, E), 256>>>(x, w1, w3, w2);
    gemm2_kernel<<<dim3(H / BN2, T / BM2, E), 256, G2_BYTES>>>(out);
}

// round 16
// speedup vs baseline: 1.0295x; 1.0043x over previous
#include <cuda_runtime.h>
#include <cuda_fp16.h>
#include <math.h>
#include <stdint.h>

#define H 1024
#define F 2048
#define E 8
#define T 2048

// ---- gemm1 tiles (R6/R13) ----
#define BM 128
#define BN 64
#define BK 32
#define SPH 40   // smem row stride in halfs; ldmatrix conflict-free

// ---- gemm2 tiles (R13): BK=64, 3-stage ----
#define BM2 128
#define BN2 128
#define BK2 64
#define SPH2 72
#define NSTG2 3

#define G2_AST (BM2 * SPH2)
#define G2_BST (BN2 * SPH2)
#define G2_A(s)  ((s) * G2_AST)
#define G2_B(s)  (NSTG2 * G2_AST + (s) * G2_BST)
#define G2_BYTES ((NSTG2 * (G2_AST + G2_BST)) * 2)   // 110592

// ---- scratch (device globals: allocation-free per harness rules) ----
__device__ int    g_cnt[E];
__device__ int    g_tok[E * T];
__device__ float  g_wgt[E * T];
__device__ __half g_mid[(size_t)E * T * F];   // [E][T][F] fp16 compacted rows
__device__ __half g_w2h[(size_t)E * H * F];   // fp16 copy of w2 (filled in gemm1)

// ---------------------------------------------------------------
__device__ __forceinline__ void ldsm4(unsigned r[4], const __half* p) {
    unsigned a = (unsigned)__cvta_generic_to_shared(p);
    asm volatile("ldmatrix.sync.aligned.m8n8.x4.shared.b16 {%0,%1,%2,%3}, [%4];"
                 : "=r"(r[0]), "=r"(r[1]), "=r"(r[2]), "=r"(r[3]) : "r"(a));
}
__device__ __forceinline__ void mma16(float c[4], const unsigned a[4], unsigned b0, unsigned b1) {
    asm volatile(
        "mma.sync.aligned.m16n8k16.row.col.f32.f16.f16.f32 "
        "{%0,%1,%2,%3},{%4,%5,%6,%7},{%8,%9},{%0,%1,%2,%3};"
        : "+f"(c[0]), "+f"(c[1]), "+f"(c[2]), "+f"(c[3])
        : "r"(a[0]), "r"(a[1]), "r"(a[2]), "r"(a[3]), "r"(b0), "r"(b1));
}
__device__ __forceinline__ uint2 f4h(float4 v) {
    __half2 lo = __floats2half2_rn(v.x, v.y);
    __half2 hi = __floats2half2_rn(v.z, v.w);
    uint2 r;
    r.x = *(unsigned*)&lo; r.y = *(unsigned*)&hi;
    return r;
}
__device__ __forceinline__ void cp_async16(const __half* sdst, const __half* gsrc) {
    unsigned d = (unsigned)__cvta_generic_to_shared(sdst);
    asm volatile("cp.async.cg.shared.global [%0], [%1], 16;" :: "r"(d), "l"(gsrc));
}
#define CP_COMMIT() asm volatile("cp.async.commit_group;" ::: "memory")
#define CP_WAIT0()  asm volatile("cp.async.wait_group 0;" ::: "memory")
#define CP_WAIT1()  asm volatile("cp.async.wait_group 1;" ::: "memory")

// ---------------------------------------------------------------
__global__ void zero_cnt_kernel() {
    if (threadIdx.x < E) g_cnt[threadIdx.x] = 0;
}

// ---------------------------------------------------------------
// Router (R16): one block of 128 threads per token -> 2048 blocks.
__global__ __launch_bounds__(128) void router_kernel(
    const float* __restrict__ x, const float* __restrict__ gw,
    float* __restrict__ logits_out)
{
    const int t   = blockIdx.x;
    const int tid = threadIdx.x;
    const int lane = tid & 31, warp = tid >> 5;
    const float4* xr  = (const float4*)(x + (size_t)t * H);
    const float4* gw4 = (const float4*)gw;

    // each thread covers float4 slots tid and tid+128 (256 total)
    float4 xv0 = xr[tid];
    float4 xv1 = xr[tid + 128];

    float acc[E];
#pragma unroll
    for (int e = 0; e < E; e++) {
        float4 g0 = gw4[e * 256 + tid];
        float4 g1 = gw4[e * 256 + tid + 128];
        acc[e] = xv0.x * g0.x + xv0.y * g0.y + xv0.z * g0.z + xv0.w * g0.w
               + xv1.x * g1.x + xv1.y * g1.y + xv1.z * g1.z + xv1.w * g1.w;
    }
#pragma unroll
    for (int e = 0; e < E; e++)
#pragma unroll
        for (int o = 16; o > 0; o >>= 1)
            acc[e] += __shfl_xor_sync(0xffffffffu, acc[e], o);

    __shared__ float s[4][E];
    if (lane == 0) {
#pragma unroll
        for (int e = 0; e < E; e++) s[warp][e] = acc[e];
    }
    __syncthreads();

    if (tid == 0) {
        float l[E];
#pragma unroll
        for (int e = 0; e < E; e++) l[e] = s[0][e] + s[1][e] + s[2][e] + s[3][e];
        if (logits_out) {
#pragma unroll
            for (int e = 0; e < E; e++) logits_out[(size_t)t * E + e] = l[e];
        }
        int i1 = 0;
#pragma unroll
        for (int e = 1; e < E; e++) if (l[e] > l[i1]) i1 = e;
        int i2 = -1;
#pragma unroll
        for (int e = 0; e < E; e++) {
            if (e == i1) continue;
            if (i2 < 0 || l[e] > l[i2]) i2 = e;
        }
        float wa = 1.f / (1.f + expf(l[i2] - l[i1]));
        float wb = 1.f - wa;
        int s1 = atomicAdd(&g_cnt[i1], 1);
        g_tok[i1 * T + s1] = t; g_wgt[i1 * T + s1] = wa;
        int s2 = atomicAdd(&g_cnt[i2], 1);
        g_tok[i2 * T + s2] = t; g_wgt[i2 * T + s2] = wb;
    }
}

// ---------------------------------------------------------------
// GEMM1 (R13): R6 structure + fused w2 fp32->fp16 conversion prologue.
// Grid must be exactly 4096 blocks (32 x 16 x 8): each converts 1024 float4 of w2.
__global__ __launch_bounds__(256, 2) void gemm1_kernel(
    const float* __restrict__ x,
    const float* __restrict__ w1,
    const float* __restrict__ w3,
    const float* __restrict__ w2)
{
    const int tid  = threadIdx.x;

    // ---- w2 conversion share (before any early exit) ----
    {
        int bflat = blockIdx.x + gridDim.x * (blockIdx.y + gridDim.y * blockIdx.z);
        const float4* src = (const float4*)w2 + (size_t)bflat * 1024;
        uint2* dst = (uint2*)g_w2h + (size_t)bflat * 1024;
#pragma unroll
        for (int j = 0; j < 4; j++)
            dst[j * 256 + tid] = f4h(src[j * 256 + tid]);
    }

    const int e  = blockIdx.z;
    const int n0 = blockIdx.x * BN;
    const int m0 = blockIdx.y * BM;
    const int ne = g_cnt[e];
    if (m0 >= ne) return;

    __shared__ __align__(16) __half sA [2][BM * SPH];
    __shared__ __align__(16) __half sB1[2][BN * SPH];
    __shared__ __align__(16) __half sB3[2][BN * SPH];

    const int lane = tid & 31, wid = tid >> 5;
    const int wm   = (wid & 3) * 32, wn = (wid >> 2) * 32;

    const int lrow = tid >> 3, lc4 = tid & 7;

    const float* ap[4];
#pragma unroll
    for (int r = 0; r < 4; r++) {
        int m = m0 + lrow + 32 * r;
        int idx = (m < ne) ? m : (ne - 1);
        ap[r] = x + (size_t)g_tok[e * T + idx] * H + lc4 * 4;
    }
    const float* b1p[2];
    const float* b3p[2];
#pragma unroll
    for (int r = 0; r < 2; r++) {
        b1p[r] = w1 + ((size_t)e * F + n0 + lrow + 32 * r) * H + lc4 * 4;
        b3p[r] = w3 + ((size_t)e * F + n0 + lrow + 32 * r) * H + lc4 * 4;
    }

    float4 va[4], vb1[2], vb3[2];
    float acc1[2][4][4] = {}, acc3[2][4][4] = {};

#pragma unroll
    for (int r = 0; r < 4; r++) va[r] = *(const float4*)(ap[r]);
#pragma unroll
    for (int r = 0; r < 2; r++) { vb1[r] = *(const float4*)(b1p[r]); vb3[r] = *(const float4*)(b3p[r]); }
#pragma unroll
    for (int r = 0; r < 4; r++) *(uint2*)&sA[0][(lrow + 32 * r) * SPH + lc4 * 4] = f4h(va[r]);
#pragma unroll
    for (int r = 0; r < 2; r++) {
        *(uint2*)&sB1[0][(lrow + 32 * r) * SPH + lc4 * 4] = f4h(vb1[r]);
        *(uint2*)&sB3[0][(lrow + 32 * r) * SPH + lc4 * 4] = f4h(vb3[r]);
    }
    __syncthreads();

    int cur = 0;
    for (int chunk = 1; chunk <= H / BK; chunk++) {
        if (chunk < H / BK) {
            int k0 = chunk * BK;
#pragma unroll
            for (int r = 0; r < 4; r++) va[r] = *(const float4*)(ap[r] + k0);
#pragma unroll
            for (int r = 0; r < 2; r++) { vb1[r] = *(const float4*)(b1p[r] + k0); vb3[r] = *(const float4*)(b3p[r] + k0); }
        }
#pragma unroll
        for (int kk = 0; kk < BK; kk += 16) {
            unsigned a[2][4];
#pragma unroll
            for (int mt = 0; mt < 2; mt++)
                ldsm4(a[mt], &sA[cur][(wm + mt * 16 + (lane & 15)) * SPH + kk + (lane >> 4) * 8]);
            unsigned b1f[2][4], b3f[2][4];
#pragma unroll
            for (int bh = 0; bh < 2; bh++) {
                int row = wn + bh * 16 + ((lane >> 4) & 1) * 8 + (lane & 7);
                int col = kk + ((lane >> 3) & 1) * 8;
                ldsm4(b1f[bh], &sB1[cur][row * SPH + col]);
                ldsm4(b3f[bh], &sB3[cur][row * SPH + col]);
            }
#pragma unroll
            for (int mt = 0; mt < 2; mt++)
#pragma unroll
                for (int nt = 0; nt < 4; nt++) {
                    int bh = nt >> 1, pr = (nt & 1) * 2;
                    mma16(acc1[mt][nt], a[mt], b1f[bh][pr], b1f[bh][pr + 1]);
                    mma16(acc3[mt][nt], a[mt], b3f[bh][pr], b3f[bh][pr + 1]);
                }
        }
        if (chunk < H / BK) {
            int nxt = cur ^ 1;
#pragma unroll
            for (int r = 0; r < 4; r++) *(uint2*)&sA[nxt][(lrow + 32 * r) * SPH + lc4 * 4] = f4h(va[r]);
#pragma unroll
            for (int r = 0; r < 2; r++) {
                *(uint2*)&sB1[nxt][(lrow + 32 * r) * SPH + lc4 * 4] = f4h(vb1[r]);
                *(uint2*)&sB3[nxt][(lrow + 32 * r) * SPH + lc4 * 4] = f4h(vb3[r]);
            }
            __syncthreads();
            cur = nxt;
        }
    }

    const int g = lane >> 2, tg = lane & 3;
#pragma unroll
    for (int mt = 0; mt < 2; mt++)
#pragma unroll
        for (int half = 0; half < 2; half++) {
            int m = m0 + wm + mt * 16 + g + half * 8;
            if (m >= ne) continue;
            __half* dst = g_mid + ((size_t)e * T + m) * F + n0 + wn;
#pragma unroll
            for (int nt = 0; nt < 4; nt++) {
                float h0 = acc1[mt][nt][half * 2 + 0];
                float h1 = acc1[mt][nt][half * 2 + 1];
                float g0 = acc3[mt][nt][half * 2 + 0];
                float g1 = acc3[mt][nt][half * 2 + 1];
                float r0 = h0 / (1.f + __expf(-h0)) * g0;
                float r1 = h1 / (1.f + __expf(-h1)) * g1;
                __half2 v = __floats2half2_rn(r0, r1);
                *(__half2*)(dst + nt * 8 + tg * 2) = v;
            }
        }
}

// ---------------------------------------------------------------
// GEMM2 (R13, unchanged): BK=64, 3 stages, all cp.async from fp16 buffers.
__global__ __launch_bounds__(256, 2) void gemm2_kernel(
    float* __restrict__ out)
{
    extern __shared__ __align__(16) __half sm[];
    const int e  = blockIdx.z;
    const int n0 = blockIdx.x * BN2;
    const int m0 = blockIdx.y * BM2;
    const int ne = g_cnt[e];
    if (m0 >= ne) return;

    const int tid  = threadIdx.x;
    const int lane = tid & 31, wid = tid >> 5;
    const int wm   = (wid & 3) * 32, wn = (wid >> 2) * 64;

    const int lrow = tid >> 3, lc8 = (tid & 7) * 8;
    const __half* amb = g_mid + ((size_t)e * T + m0 + lrow) * F + lc8;
    const __half* bmb = g_w2h + ((size_t)e * H + n0 + lrow) * F + lc8;

    float acc[2][8][4] = {};

#pragma unroll
    for (int s = 0; s < 2; s++) {
#pragma unroll
        for (int i = 0; i < 4; i++) {
            int row = lrow + 32 * i;
            cp_async16(&sm[G2_A(s) + row * SPH2 + lc8], amb + (size_t)(32 * i) * F + s * BK2);
            cp_async16(&sm[G2_B(s) + row * SPH2 + lc8], bmb + (size_t)(32 * i) * F + s * BK2);
        }
        CP_COMMIT();
    }
    CP_WAIT1();
    __syncthreads();

    const int NC = F / BK2;   // 32
    int cur = 0;
    for (int c = 0; c < NC; c++) {
        const bool have2 = (c + 2 < NC);
        if (have2) {
            int s = (cur + 2) % NSTG2;
            int k0 = (c + 2) * BK2;
#pragma unroll
            for (int i = 0; i < 4; i++) {
                int row = lrow + 32 * i;
                cp_async16(&sm[G2_A(s) + row * SPH2 + lc8], amb + (size_t)(32 * i) * F + k0);
                cp_async16(&sm[G2_B(s) + row * SPH2 + lc8], bmb + (size_t)(32 * i) * F + k0);
            }
            CP_COMMIT();
        }

#pragma unroll
        for (int kk = 0; kk < BK2; kk += 16) {
            unsigned a[2][4];
#pragma unroll
            for (int mt = 0; mt < 2; mt++)
                ldsm4(a[mt], &sm[G2_A(cur) + (wm + mt * 16 + (lane & 15)) * SPH2 + kk + (lane >> 4) * 8]);
            unsigned bf[4][4];
#pragma unroll
            for (int bh = 0; bh < 4; bh++) {
                int row = wn + bh * 16 + ((lane >> 4) & 1) * 8 + (lane & 7);
                int col = kk + ((lane >> 3) & 1) * 8;
                ldsm4(bf[bh], &sm[G2_B(cur) + row * SPH2 + col]);
            }
#pragma unroll
            for (int mt = 0; mt < 2; mt++)
#pragma unroll
                for (int nt = 0; nt < 8; nt++) {
                    int bh = nt >> 1, pr = (nt & 1) * 2;
                    mma16(acc[mt][nt], a[mt], bf[bh][pr], bf[bh][pr + 1]);
                }
        }

        if (c + 1 < NC) {
            if (have2) CP_WAIT1(); else CP_WAIT0();
            __syncthreads();
            cur = (cur + 1 == NSTG2) ? 0 : cur + 1;
        }
    }

    const int g = lane >> 2, tg = lane & 3;
#pragma unroll
    for (int mt = 0; mt < 2; mt++)
#pragma unroll
        for (int half = 0; half < 2; half++) {
            int m = m0 + wm + mt * 16 + g + half * 8;
            if (m >= ne) continue;
            int   tok = g_tok[e * T + m];
            float w   = g_wgt[e * T + m];
            float* dst = out + (size_t)tok * H + n0 + wn;
#pragma unroll
            for (int nt = 0; nt < 8; nt++) {
                atomicAdd(dst + nt * 8 + tg * 2 + 0, w * acc[mt][nt][half * 2 + 0]);
                atomicAdd(dst + nt * 8 + tg * 2 + 1, w * acc[mt][nt][half * 2 + 1]);
            }
        }
}

// ---------------------------------------------------------------
extern "C" void kernel_launch(void* const* d_in, const int* in_sizes, int n_in,
                              void* d_out, int out_size)
{
    const float* x  = (const float*)d_in[0];
    const float* gw = (const float*)d_in[1];
    const float* w1 = (const float*)d_in[2];
    const float* w2 = (const float*)d_in[3];
    const float* w3 = (const float*)d_in[4];
    float* out = (float*)d_out;

    static int configured = 0;
    if (!configured) {
        cudaFuncSetAttribute(gemm2_kernel,
            cudaFuncAttributeMaxDynamicSharedMemorySize, G2_BYTES);
        configured = 1;
    }

    const size_t main_sz = (size_t)T * H;
    float* logits = ((size_t)out_size >= main_sz + (size_t)T * E)
                        ? out + main_sz : nullptr;

    cudaMemsetAsync(d_out, 0, (size_t)out_size * sizeof(float));
    zero_cnt_kernel<<<1, 32>>>();
    router_kernel<<<T, 128>>>(x, gw, logits);
    // grid = 32*16*8 = 4096 blocks; each converts 1024 float4 of w2
    gemm1_kernel<<<dim3(F / BN, T / BM, E), 256>>>(x, w1, w3, w2);
    gemm2_kernel<<<dim3(H / BN2, T / BM2, E), 256, G2_BYTES>>>(out);
}

// round 17
// speedup vs baseline: 1.0559x; 1.0256x over previous
#include <cuda_runtime.h>
#include <cuda_fp16.h>
#include <math.h>
#include <stdint.h>

#define H 1024
#define F 2048
#define E 8
#define T 2048

// ---- gemm1 tiles (R6/R13) ----
#define BM 128
#define BN 64
#define BK 32
#define SPH 40   // smem row stride in halfs; ldmatrix conflict-free

// ---- gemm2 tiles (R13): BK=64, 3-stage ----
#define BM2 128
#define BN2 128
#define BK2 64
#define SPH2 72
#define NSTG2 3

#define G2_AST (BM2 * SPH2)
#define G2_BST (BN2 * SPH2)
#define G2_A(s)  ((s) * G2_AST)
#define G2_B(s)  (NSTG2 * G2_AST + (s) * G2_BST)
#define G2_BYTES ((NSTG2 * (G2_AST + G2_BST)) * 2)   // 110592

// ---- scratch (device globals: allocation-free per harness rules) ----
__device__ int    g_cnt[E];
__device__ int    g_tok[E * T];
__device__ float  g_wgt[E * T];
__device__ __half g_mid[(size_t)E * T * F];   // [E][T][F] fp16 compacted rows
__device__ __half g_w2h[(size_t)E * H * F];   // fp16 copy of w2 (filled in gemm1)

// ---------------------------------------------------------------
__device__ __forceinline__ void ldsm4(unsigned r[4], const __half* p) {
    unsigned a = (unsigned)__cvta_generic_to_shared(p);
    asm volatile("ldmatrix.sync.aligned.m8n8.x4.shared.b16 {%0,%1,%2,%3}, [%4];"
                 : "=r"(r[0]), "=r"(r[1]), "=r"(r[2]), "=r"(r[3]) : "r"(a));
}
__device__ __forceinline__ void mma16(float c[4], const unsigned a[4], unsigned b0, unsigned b1) {
    asm volatile(
        "mma.sync.aligned.m16n8k16.row.col.f32.f16.f16.f32 "
        "{%0,%1,%2,%3},{%4,%5,%6,%7},{%8,%9},{%0,%1,%2,%3};"
        : "+f"(c[0]), "+f"(c[1]), "+f"(c[2]), "+f"(c[3])
        : "r"(a[0]), "r"(a[1]), "r"(a[2]), "r"(a[3]), "r"(b0), "r"(b1));
}
__device__ __forceinline__ uint2 f4h(float4 v) {
    __half2 lo = __floats2half2_rn(v.x, v.y);
    __half2 hi = __floats2half2_rn(v.z, v.w);
    uint2 r;
    r.x = *(unsigned*)&lo; r.y = *(unsigned*)&hi;
    return r;
}
__device__ __forceinline__ void cp_async16(const __half* sdst, const __half* gsrc) {
    unsigned d = (unsigned)__cvta_generic_to_shared(sdst);
    asm volatile("cp.async.cg.shared.global [%0], [%1], 16;" :: "r"(d), "l"(gsrc));
}
#define CP_COMMIT() asm volatile("cp.async.commit_group;" ::: "memory")
#define CP_WAIT0()  asm volatile("cp.async.wait_group 0;" ::: "memory")
#define CP_WAIT1()  asm volatile("cp.async.wait_group 1;" ::: "memory")

// ---------------------------------------------------------------
__global__ void zero_cnt_kernel() {
    if (threadIdx.x < E) g_cnt[threadIdx.x] = 0;
}

// ---------------------------------------------------------------
// Router (R13): one warp per token.
__global__ __launch_bounds__(256) void router_kernel(
    const float* __restrict__ x, const float* __restrict__ gw,
    float* __restrict__ logits_out)
{
    const int t    = blockIdx.x * 8 + (threadIdx.x >> 5);
    const int lane = threadIdx.x & 31;
    const float4* xr  = (const float4*)(x + (size_t)t * H);
    const float4* gw4 = (const float4*)gw;

    float acc[E];
#pragma unroll
    for (int e = 0; e < E; e++) acc[e] = 0.f;

#pragma unroll
    for (int i = 0; i < 8; i++) {
        float4 xv = xr[i * 32 + lane];
#pragma unroll
        for (int e = 0; e < E; e++) {
            float4 g = gw4[e * 256 + i * 32 + lane];
            acc[e] += xv.x * g.x + xv.y * g.y + xv.z * g.z + xv.w * g.w;
        }
    }
#pragma unroll
    for (int e = 0; e < E; e++)
#pragma unroll
        for (int o = 16; o > 0; o >>= 1)
            acc[e] += __shfl_xor_sync(0xffffffffu, acc[e], o);

    if (lane == 0) {
        if (logits_out)
#pragma unroll
            for (int e = 0; e < E; e++) logits_out[(size_t)t * E + e] = acc[e];
        int i1 = 0;
#pragma unroll
        for (int e = 1; e < E; e++) if (acc[e] > acc[i1]) i1 = e;
        int i2 = -1;
#pragma unroll
        for (int e = 0; e < E; e++) {
            if (e == i1) continue;
            if (i2 < 0 || acc[e] > acc[i2]) i2 = e;
        }
        float wa = 1.f / (1.f + expf(acc[i2] - acc[i1]));
        float wb = 1.f - wa;
        int s1 = atomicAdd(&g_cnt[i1], 1);
        g_tok[i1 * T + s1] = t; g_wgt[i1 * T + s1] = wa;
        int s2 = atomicAdd(&g_cnt[i2], 1);
        g_tok[i2 * T + s2] = t; g_wgt[i2 * T + s2] = wb;
    }
}

// ---------------------------------------------------------------
// GEMM1 (R17): R6 structure; w2 fp32->fp16 conversion done ONLY by blocks
// with blockIdx.y >= 8 (early-exit blocks when ne <= 1024 — always true for
// balanced routing; if ne > 1024 those blocks also compute, still correct).
// Conv coverage: 32(n) x 8(y-8) x 8(e) = 2048 blocks x 2048 float4 = E*H*F/4.
__global__ __launch_bounds__(256, 2) void gemm1_kernel(
    const float* __restrict__ x,
    const float* __restrict__ w1,
    const float* __restrict__ w3,
    const float* __restrict__ w2)
{
    const int tid = threadIdx.x;

    if (blockIdx.y >= 8) {
        int bflat = blockIdx.x + 32 * ((blockIdx.y - 8) + 8 * blockIdx.z);
        const float4* src = (const float4*)w2 + (size_t)bflat * 2048;
        uint2* dst = (uint2*)g_w2h + (size_t)bflat * 2048;
#pragma unroll
        for (int j = 0; j < 8; j++)
            dst[j * 256 + tid] = f4h(src[j * 256 + tid]);
    }

    const int e  = blockIdx.z;
    const int n0 = blockIdx.x * BN;
    const int m0 = blockIdx.y * BM;
    const int ne = g_cnt[e];
    if (m0 >= ne) return;

    __shared__ __align__(16) __half sA [2][BM * SPH];
    __shared__ __align__(16) __half sB1[2][BN * SPH];
    __shared__ __align__(16) __half sB3[2][BN * SPH];

    const int lane = tid & 31, wid = tid >> 5;
    const int wm   = (wid & 3) * 32, wn = (wid >> 2) * 32;

    const int lrow = tid >> 3, lc4 = tid & 7;

    const float* ap[4];
#pragma unroll
    for (int r = 0; r < 4; r++) {
        int m = m0 + lrow + 32 * r;
        int idx = (m < ne) ? m : (ne - 1);
        ap[r] = x + (size_t)g_tok[e * T + idx] * H + lc4 * 4;
    }
    const float* b1p[2];
    const float* b3p[2];
#pragma unroll
    for (int r = 0; r < 2; r++) {
        b1p[r] = w1 + ((size_t)e * F + n0 + lrow + 32 * r) * H + lc4 * 4;
        b3p[r] = w3 + ((size_t)e * F + n0 + lrow + 32 * r) * H + lc4 * 4;
    }

    float4 va[4], vb1[2], vb3[2];
    float acc1[2][4][4] = {}, acc3[2][4][4] = {};

#pragma unroll
    for (int r = 0; r < 4; r++) va[r] = *(const float4*)(ap[r]);
#pragma unroll
    for (int r = 0; r < 2; r++) { vb1[r] = *(const float4*)(b1p[r]); vb3[r] = *(const float4*)(b3p[r]); }
#pragma unroll
    for (int r = 0; r < 4; r++) *(uint2*)&sA[0][(lrow + 32 * r) * SPH + lc4 * 4] = f4h(va[r]);
#pragma unroll
    for (int r = 0; r < 2; r++) {
        *(uint2*)&sB1[0][(lrow + 32 * r) * SPH + lc4 * 4] = f4h(vb1[r]);
        *(uint2*)&sB3[0][(lrow + 32 * r) * SPH + lc4 * 4] = f4h(vb3[r]);
    }
    __syncthreads();

    int cur = 0;
    for (int chunk = 1; chunk <= H / BK; chunk++) {
        if (chunk < H / BK) {
            int k0 = chunk * BK;
#pragma unroll
            for (int r = 0; r < 4; r++) va[r] = *(const float4*)(ap[r] + k0);
#pragma unroll
            for (int r = 0; r < 2; r++) { vb1[r] = *(const float4*)(b1p[r] + k0); vb3[r] = *(const float4*)(b3p[r] + k0); }
        }
#pragma unroll
        for (int kk = 0; kk < BK; kk += 16) {
            unsigned a[2][4];
#pragma unroll
            for (int mt = 0; mt < 2; mt++)
                ldsm4(a[mt], &sA[cur][(wm + mt * 16 + (lane & 15)) * SPH + kk + (lane >> 4) * 8]);
            unsigned b1f[2][4], b3f[2][4];
#pragma unroll
            for (int bh = 0; bh < 2; bh++) {
                int row = wn + bh * 16 + ((lane >> 4) & 1) * 8 + (lane & 7);
                int col = kk + ((lane >> 3) & 1) * 8;
                ldsm4(b1f[bh], &sB1[cur][row * SPH + col]);
                ldsm4(b3f[bh], &sB3[cur][row * SPH + col]);
            }
#pragma unroll
            for (int mt = 0; mt < 2; mt++)
#pragma unroll
                for (int nt = 0; nt < 4; nt++) {
                    int bh = nt >> 1, pr = (nt & 1) * 2;
                    mma16(acc1[mt][nt], a[mt], b1f[bh][pr], b1f[bh][pr + 1]);
                    mma16(acc3[mt][nt], a[mt], b3f[bh][pr], b3f[bh][pr + 1]);
                }
        }
        if (chunk < H / BK) {
            int nxt = cur ^ 1;
#pragma unroll
            for (int r = 0; r < 4; r++) *(uint2*)&sA[nxt][(lrow + 32 * r) * SPH + lc4 * 4] = f4h(va[r]);
#pragma unroll
            for (int r = 0; r < 2; r++) {
                *(uint2*)&sB1[nxt][(lrow + 32 * r) * SPH + lc4 * 4] = f4h(vb1[r]);
                *(uint2*)&sB3[nxt][(lrow + 32 * r) * SPH + lc4 * 4] = f4h(vb3[r]);
            }
            __syncthreads();
            cur = nxt;
        }
    }

    const int g = lane >> 2, tg = lane & 3;
#pragma unroll
    for (int mt = 0; mt < 2; mt++)
#pragma unroll
        for (int half = 0; half < 2; half++) {
            int m = m0 + wm + mt * 16 + g + half * 8;
            if (m >= ne) continue;
            __half* dst = g_mid + ((size_t)e * T + m) * F + n0 + wn;
#pragma unroll
            for (int nt = 0; nt < 4; nt++) {
                float h0 = acc1[mt][nt][half * 2 + 0];
                float h1 = acc1[mt][nt][half * 2 + 1];
                float g0 = acc3[mt][nt][half * 2 + 0];
                float g1 = acc3[mt][nt][half * 2 + 1];
                float r0 = h0 / (1.f + __expf(-h0)) * g0;
                float r1 = h1 / (1.f + __expf(-h1)) * g1;
                __half2 v = __floats2half2_rn(r0, r1);
                *(__half2*)(dst + nt * 8 + tg * 2) = v;
            }
        }
}

// ---------------------------------------------------------------
// GEMM2 (R13, unchanged): BK=64, 3 stages, all cp.async from fp16 buffers.
__global__ __launch_bounds__(256, 2) void gemm2_kernel(
    float* __restrict__ out)
{
    extern __shared__ __align__(16) __half sm[];
    const int e  = blockIdx.z;
    const int n0 = blockIdx.x * BN2;
    const int m0 = blockIdx.y * BM2;
    const int ne = g_cnt[e];
    if (m0 >= ne) return;

    const int tid  = threadIdx.x;
    const int lane = tid & 31, wid = tid >> 5;
    const int wm   = (wid & 3) * 32, wn = (wid >> 2) * 64;

    const int lrow = tid >> 3, lc8 = (tid & 7) * 8;
    const __half* amb = g_mid + ((size_t)e * T + m0 + lrow) * F + lc8;
    const __half* bmb = g_w2h + ((size_t)e * H + n0 + lrow) * F + lc8;

    float acc[2][8][4] = {};

#pragma unroll
    for (int s = 0; s < 2; s++) {
#pragma unroll
        for (int i = 0; i < 4; i++) {
            int row = lrow + 32 * i;
            cp_async16(&sm[G2_A(s) + row * SPH2 + lc8], amb + (size_t)(32 * i) * F + s * BK2);
            cp_async16(&sm[G2_B(s) + row * SPH2 + lc8], bmb + (size_t)(32 * i) * F + s * BK2);
        }
        CP_COMMIT();
    }
    CP_WAIT1();
    __syncthreads();

    const int NC = F / BK2;   // 32
    int cur = 0;
    for (int c = 0; c < NC; c++) {
        const bool have2 = (c + 2 < NC);
        if (have2) {
            int s = (cur + 2) % NSTG2;
            int k0 = (c + 2) * BK2;
#pragma unroll
            for (int i = 0; i < 4; i++) {
                int row = lrow + 32 * i;
                cp_async16(&sm[G2_A(s) + row * SPH2 + lc8], amb + (size_t)(32 * i) * F + k0);
                cp_async16(&sm[G2_B(s) + row * SPH2 + lc8], bmb + (size_t)(32 * i) * F + k0);
            }
            CP_COMMIT();
        }

#pragma unroll
        for (int kk = 0; kk < BK2; kk += 16) {
            unsigned a[2][4];
#pragma unroll
            for (int mt = 0; mt < 2; mt++)
                ldsm4(a[mt], &sm[G2_A(cur) + (wm + mt * 16 + (lane & 15)) * SPH2 + kk + (lane >> 4) * 8]);
            unsigned bf[4][4];
#pragma unroll
            for (int bh = 0; bh < 4; bh++) {
                int row = wn + bh * 16 + ((lane >> 4) & 1) * 8 + (lane & 7);
                int col = kk + ((lane >> 3) & 1) * 8;
                ldsm4(bf[bh], &sm[G2_B(cur) + row * SPH2 + col]);
            }
#pragma unroll
            for (int mt = 0; mt < 2; mt++)
#pragma unroll
                for (int nt = 0; nt < 8; nt++) {
                    int bh = nt >> 1, pr = (nt & 1) * 2;
                    mma16(acc[mt][nt], a[mt], bf[bh][pr], bf[bh][pr + 1]);
                }
        }

        if (c + 1 < NC) {
            if (have2) CP_WAIT1(); else CP_WAIT0();
            __syncthreads();
            cur = (cur + 1 == NSTG2) ? 0 : cur + 1;
        }
    }

    const int g = lane >> 2, tg = lane & 3;
#pragma unroll
    for (int mt = 0; mt < 2; mt++)
#pragma unroll
        for (int half = 0; half < 2; half++) {
            int m = m0 + wm + mt * 16 + g + half * 8;
            if (m >= ne) continue;
            int   tok = g_tok[e * T + m];
            float w   = g_wgt[e * T + m];
            float* dst = out + (size_t)tok * H + n0 + wn;
#pragma unroll
            for (int nt = 0; nt < 8; nt++) {
                atomicAdd(dst + nt * 8 + tg * 2 + 0, w * acc[mt][nt][half * 2 + 0]);
                atomicAdd(dst + nt * 8 + tg * 2 + 1, w * acc[mt][nt][half * 2 + 1]);
            }
        }
}

// ---------------------------------------------------------------
extern "C" void kernel_launch(void* const* d_in, const int* in_sizes, int n_in,
                              void* d_out, int out_size)
{
    const float* x  = (const float*)d_in[0];
    const float* gw = (const float*)d_in[1];
    const float* w1 = (const float*)d_in[2];
    const float* w2 = (const float*)d_in[3];
    const float* w3 = (const float*)d_in[4];
    float* out = (float*)d_out;

    static int configured = 0;
    if (!configured) {
        cudaFuncSetAttribute(gemm2_kernel,
            cudaFuncAttributeMaxDynamicSharedMemorySize, G2_BYTES);
        configured = 1;
    }

    const size_t main_sz = (size_t)T * H;
    float* logits = ((size_t)out_size >= main_sz + (size_t)T * E)
                        ? out + main_sz : nullptr;

    cudaMemsetAsync(d_out, 0, (size_t)out_size * sizeof(float));
    zero_cnt_kernel<<<1, 32>>>();
    router_kernel<<<T / 8, 256>>>(x, gw, logits);
    // grid = 32*16*8 = 4096 blocks; blocks with y>=8 convert w2 (2048 float4 each)
    gemm1_kernel<<<dim3(F / BN, T / BM, E), 256>>>(x, w1, w3, w2);
    gemm2_kernel<<<dim3(H / BN2, T / BM2, E), 256, G2_BYTES>>>(out);
}